// round 2
// baseline (speedup 1.0000x reference)
#include <cuda_runtime.h>
#include <math.h>

#define N_TOK   32768
#define C_DIM   1024
#define C3      3072
#define H_HEADS 16
#define D_HEAD  64
#define NW      64          // (32/8)^3 windows
#define WSZ     512         // 8^3 tokens per window
#define KST     68          // padded smem stride (floats) for K/P tile

// ---------------- scratch (device globals: no allocation allowed) ----------
__device__ float g_qkv[(size_t)N_TOK * C3];
__device__ float g_qw [(size_t)NW * H_HEADS * WSZ * D_HEAD];
__device__ float g_kw [(size_t)NW * H_HEADS * WSZ * D_HEAD];
__device__ float g_vw [(size_t)NW * H_HEADS * WSZ * D_HEAD];
__device__ float g_h  [(size_t)N_TOK * C_DIM];

// ---------------- K1/K4: 128x128x8 SGEMM, C = A@B + bias -------------------
// A: [M,K] row-major, B: [K,N] row-major. M,N,K multiples of 128/128/8.
// Register prefetch of the next k-slice overlaps GMEM latency with FMAs.
__global__ __launch_bounds__(256) void sgemm128(
        const float* __restrict__ A, const float* __restrict__ B,
        const float* __restrict__ bias, float* __restrict__ Cmat,
        int M, int Nn, int K)
{
    __shared__ float As[8][132];   // A^T tile, padded: conflict-free transpose
    __shared__ float Bs[8][128];

    const int t  = threadIdx.x;
    const int m0 = blockIdx.y * 128;
    const int n0 = blockIdx.x * 128;

    const int arow = t >> 1;            // 0..127
    const int acol = (t & 1) * 4;       // 0 or 4
    const int brow = t >> 5;            // 0..7
    const int bcol = (t & 31) * 4;      // 0..124

    const int w   = t >> 5;
    const int lne = t & 31;
    const int mf  = (w & 3) * 32 + (lne & 3) * 8;   // 8-row fragment
    const int nf  = (w >> 2) * 64 + (lne >> 2) * 8; // 8-col fragment

    const float* Ap = A + (size_t)(m0 + arow) * K + acol;
    const float* Bp = B + (size_t)brow * Nn + n0 + bcol;

    float acc[8][8] = {};

    float4 av = *(const float4*)(Ap);
    float4 bv = *(const float4*)(Bp);

    for (int k0 = 0; k0 < K; k0 += 8) {
        As[acol + 0][arow] = av.x;
        As[acol + 1][arow] = av.y;
        As[acol + 2][arow] = av.z;
        As[acol + 3][arow] = av.w;
        *(float4*)&Bs[brow][bcol] = bv;
        __syncthreads();

        if (k0 + 8 < K) {                 // prefetch next slice during FMAs
            av = *(const float4*)(Ap + k0 + 8);
            bv = *(const float4*)(Bp + (size_t)(k0 + 8) * Nn);
        }

        #pragma unroll
        for (int k = 0; k < 8; k++) {
            float ar[8], br[8];
            *(float4*)&ar[0] = *(const float4*)&As[k][mf];
            *(float4*)&ar[4] = *(const float4*)&As[k][mf + 4];
            *(float4*)&br[0] = *(const float4*)&Bs[k][nf];
            *(float4*)&br[4] = *(const float4*)&Bs[k][nf + 4];
            #pragma unroll
            for (int i = 0; i < 8; i++)
                #pragma unroll
                for (int j = 0; j < 8; j++)
                    acc[i][j] = fmaf(ar[i], br[j], acc[i][j]);
        }
        __syncthreads();
    }

    float bb[8];
    #pragma unroll
    for (int j = 0; j < 8; j++) bb[j] = bias[n0 + nf + j];
    #pragma unroll
    for (int i = 0; i < 8; i++) {
        float* cp = Cmat + (size_t)(m0 + mf + i) * Nn + n0 + nf;
        *(float4*)cp       = make_float4(acc[i][0]+bb[0], acc[i][1]+bb[1],
                                         acc[i][2]+bb[2], acc[i][3]+bb[3]);
        *(float4*)(cp + 4) = make_float4(acc[i][4]+bb[4], acc[i][5]+bb[5],
                                         acc[i][6]+bb[6], acc[i][7]+bb[7]);
    }
}

// ---------------- K2: RMS-norm + RoPE + window scatter ---------------------
// One warp per (token n, head h). Lane l owns the rope pair (2l, 2l+1).
// Attention scale 1/sqrt(D)=1/8 is folded into q: q_net = t*gamma/norm.
__global__ __launch_bounds__(256) void k_normrope(
        const float* __restrict__ qkv,
        const float* __restrict__ gq, const float* __restrict__ gk,
        float* __restrict__ qw, float* __restrict__ kw, float* __restrict__ vw)
{
    const int t    = threadIdx.x;
    const int wid  = t >> 5;
    const int lane = t & 31;
    const int gw   = blockIdx.x * 8 + wid;      // 0 .. N_TOK*H-1
    const int n    = gw >> 4;
    const int h    = gw & 15;

    const float* p = qkv + (size_t)n * C3 + h * D_HEAD;
    float2 q = *(const float2*)(p + 2 * lane);
    float2 k = *(const float2*)(p + C_DIM + 2 * lane);
    float2 v = *(const float2*)(p + 2 * C_DIM + 2 * lane);

    float sq = q.x * q.x + q.y * q.y;
    float sk = k.x * k.x + k.y * k.y;
    #pragma unroll
    for (int m = 16; m; m >>= 1) {
        sq += __shfl_xor_sync(0xffffffffu, sq, m);
        sk += __shfl_xor_sync(0xffffffffu, sk, m);
    }
    // reference: t/norm * gamma * sqrt(D);  q additionally * 1/sqrt(D)
    const float invq = 1.0f / fmaxf(sqrtf(sq), 1e-12f);   // 8/norm * 1/8
    const float invk = 8.0f / fmaxf(sqrtf(sk), 1e-12f);

    float2 gqv = *(const float2*)(gq + h * D_HEAD + 2 * lane);
    float2 gkv = *(const float2*)(gk + h * D_HEAD + 2 * lane);
    q.x *= invq * gqv.x;  q.y *= invq * gqv.y;
    k.x *= invk * gkv.x;  k.y *= invk * gkv.y;

    // RoPE (coords derivable from n: meshgrid 'ij' flatten)
    const int gx = n >> 10, gy = (n >> 5) & 31, gz = n & 31;
    float c = 1.0f, s = 0.0f;
    if (lane < 30) {
        const int axis = lane / 10, f = lane % 10;
        // 1/10000^(f/10); ln(10000)/10 = 0.9210340371976184
        const float freq = expf(-(float)f * 0.9210340371976184f);
        const int coord = (axis == 0) ? gx : (axis == 1) ? gy : gz;
        const float ph = (float)coord * freq;
        c = cosf(ph);  s = sinf(ph);
    }
    const float q0 = q.x * c - q.y * s, q1 = q.x * s + q.y * c;
    const float k0 = k.x * c - k.y * s, k1 = k.x * s + k.y * c;

    // window scatter: layout [w][h][pos][d]
    const int wdw = ((gx >> 3) * 4 + (gy >> 3)) * 4 + (gz >> 3);
    const int pos = ((gx & 7) * 8 + (gy & 7)) * 8 + (gz & 7);
    const size_t ob = ((size_t)(wdw * H_HEADS + h) * WSZ + pos) * D_HEAD + 2 * lane;
    *(float2*)(qw + ob) = make_float2(q0, q1);
    *(float2*)(kw + ob) = make_float2(k0, k1);
    *(float2*)(vw + ob) = v;
}

// ---------------- K3: windowed flash attention -----------------------------
// Block = 256 thr, handles 64 query rows of one (window,head) slab [512,64].
// Streams 8 K/V tiles of 64 rows with online softmax.
// Thread (tx,ty) in 16x16:  S rows ty+16i, S cols tx+16j (stride-68 smem ->
// conflict-free LDS.128);  O rows ty+16i, O cols 4tx+j.  P reuses K's smem.
__global__ __launch_bounds__(256) void k_attn(
        const float* __restrict__ Q, const float* __restrict__ Kw,
        const float* __restrict__ Vw, float* __restrict__ hout)
{
    extern __shared__ float sm[];
    float* Qs = sm;                       // [64][64]
    float* Ks = sm + 64 * 64;             // [64][KST]   (reused as P)
    float* Vs = sm + 64 * 64 + 64 * KST;  // [64][64]

    const int t  = threadIdx.x;
    const int tx = t & 15, ty = t >> 4;
    const int b  = blockIdx.x;
    const int wh = b >> 3;                // window*16 + head
    const int qt = b & 7;                 // query tile
    const size_t base = (size_t)wh * WSZ * D_HEAD;

    #pragma unroll
    for (int i = 0; i < 4; i++) {         // load Q tile [64,64]
        int lin = t + 256 * i;
        int row = lin >> 4, c4 = (lin & 15) << 2;
        *(float4*)(Qs + row * 64 + c4) =
            *(const float4*)(Q + base + (size_t)(qt * 64 + row) * 64 + c4);
    }

    float m[4], l[4], O[4][4];
    #pragma unroll
    for (int i = 0; i < 4; i++) {
        m[i] = -3.0e38f; l[i] = 0.f;
        #pragma unroll
        for (int j = 0; j < 4; j++) O[i][j] = 0.f;
    }

    for (int kt = 0; kt < 8; kt++) {
        __syncthreads();                  // prev PV done / Q stores visible
        #pragma unroll
        for (int i = 0; i < 4; i++) {     // load K,V tiles [64,64]
            int lin = t + 256 * i;
            int row = lin >> 4, c4 = (lin & 15) << 2;
            size_t g = base + (size_t)(kt * 64 + row) * 64 + c4;
            *(float4*)(Ks + row * KST + c4) = *(const float4*)(Kw + g);
            *(float4*)(Vs + row * 64  + c4) = *(const float4*)(Vw + g);
        }
        __syncthreads();

        // S = Q K^T  (scale already folded into Q)
        float S[4][4];
        #pragma unroll
        for (int i = 0; i < 4; i++)
            #pragma unroll
            for (int j = 0; j < 4; j++) S[i][j] = 0.f;
        #pragma unroll
        for (int d4 = 0; d4 < 16; d4++) {
            float4 qv[4], kv[4];
            #pragma unroll
            for (int i = 0; i < 4; i++)
                qv[i] = *(const float4*)(Qs + (ty + 16 * i) * 64 + d4 * 4);
            #pragma unroll
            for (int j = 0; j < 4; j++)
                kv[j] = *(const float4*)(Ks + (tx + 16 * j) * KST + d4 * 4);
            #pragma unroll
            for (int i = 0; i < 4; i++)
                #pragma unroll
                for (int j = 0; j < 4; j++)
                    S[i][j] += qv[i].x * kv[j].x + qv[i].y * kv[j].y
                             + qv[i].z * kv[j].z + qv[i].w * kv[j].w;
        }

        // online softmax (row reductions across the 16 tx lanes)
        float alpha[4];
        #pragma unroll
        for (int i = 0; i < 4; i++) {
            float rm = fmaxf(fmaxf(S[i][0], S[i][1]), fmaxf(S[i][2], S[i][3]));
            #pragma unroll
            for (int mm = 8; mm; mm >>= 1)
                rm = fmaxf(rm, __shfl_xor_sync(0xffffffffu, rm, mm));
            float mn = fmaxf(m[i], rm);
            alpha[i] = __expf(m[i] - mn);
            m[i] = mn;
            float ps = 0.f;
            #pragma unroll
            for (int j = 0; j < 4; j++) { S[i][j] = __expf(S[i][j] - mn); ps += S[i][j]; }
            #pragma unroll
            for (int mm = 8; mm; mm >>= 1)
                ps += __shfl_xor_sync(0xffffffffu, ps, mm);
            l[i] = l[i] * alpha[i] + ps;
        }

        __syncthreads();                  // everyone done reading Ks
        #pragma unroll
        for (int i = 0; i < 4; i++)
            #pragma unroll
            for (int j = 0; j < 4; j++) {
                Ks[(ty + 16 * i) * KST + tx + 16 * j] = S[i][j];  // P tile
                O[i][j] *= alpha[i];
            }
        __syncthreads();

        // O += P V
        #pragma unroll
        for (int cc = 0; cc < 16; cc++) {
            float4 pv[4], vv[4];
            #pragma unroll
            for (int i = 0; i < 4; i++)
                pv[i] = *(const float4*)(Ks + (ty + 16 * i) * KST + cc * 4);
            #pragma unroll
            for (int c = 0; c < 4; c++)
                vv[c] = *(const float4*)(Vs + (cc * 4 + c) * 64 + tx * 4);
            #pragma unroll
            for (int i = 0; i < 4; i++) {
                O[i][0] = fmaf(pv[i].x, vv[0].x, O[i][0]);
                O[i][1] = fmaf(pv[i].x, vv[0].y, O[i][1]);
                O[i][2] = fmaf(pv[i].x, vv[0].z, O[i][2]);
                O[i][3] = fmaf(pv[i].x, vv[0].w, O[i][3]);
                O[i][0] = fmaf(pv[i].y, vv[1].x, O[i][0]);
                O[i][1] = fmaf(pv[i].y, vv[1].y, O[i][1]);
                O[i][2] = fmaf(pv[i].y, vv[1].z, O[i][2]);
                O[i][3] = fmaf(pv[i].y, vv[1].w, O[i][3]);
                O[i][0] = fmaf(pv[i].z, vv[2].x, O[i][0]);
                O[i][1] = fmaf(pv[i].z, vv[2].y, O[i][1]);
                O[i][2] = fmaf(pv[i].z, vv[2].z, O[i][2]);
                O[i][3] = fmaf(pv[i].z, vv[2].w, O[i][3]);
                O[i][0] = fmaf(pv[i].w, vv[3].x, O[i][0]);
                O[i][1] = fmaf(pv[i].w, vv[3].y, O[i][1]);
                O[i][2] = fmaf(pv[i].w, vv[3].z, O[i][2]);
                O[i][3] = fmaf(pv[i].w, vv[3].w, O[i][3]);
            }
        }
    }

    // write un-windowed output rows into g_h [N, C]
    const int wdw = wh >> 4, h = wh & 15;
    const int wx = wdw >> 4, wy = (wdw >> 2) & 3, wz = wdw & 3;
    #pragma unroll
    for (int i = 0; i < 4; i++) {
        int p  = qt * 64 + ty + 16 * i;
        int ix = p >> 6, iy = (p >> 3) & 7, iz = p & 7;
        int gx = wx * 8 + ix, gy = wy * 8 + iy, gz = wz * 8 + iz;
        int n  = (gx << 10) + (gy << 5) + gz;
        float inv = 1.0f / l[i];
        *(float4*)(hout + (size_t)n * C_DIM + h * D_HEAD + tx * 4) =
            make_float4(O[i][0] * inv, O[i][1] * inv, O[i][2] * inv, O[i][3] * inv);
    }
}

// ---------------- launch ---------------------------------------------------
extern "C" void kernel_launch(void* const* d_in, const int* in_sizes, int n_in,
                              void* d_out, int out_size)
{
    const float* x    = (const float*)d_in[0];
    // d_in[1] = coords (int32) — derivable from token index, unused
    const float* Wqkv = (const float*)d_in[2];
    const float* bqkv = (const float*)d_in[3];
    const float* gq   = (const float*)d_in[4];
    const float* gk   = (const float*)d_in[5];
    const float* Wout = (const float*)d_in[6];
    const float* bout = (const float*)d_in[7];
    float* out = (float*)d_out;

    float *qkv, *qw, *kw, *vw, *hb;
    cudaGetSymbolAddress((void**)&qkv, g_qkv);
    cudaGetSymbolAddress((void**)&qw,  g_qw);
    cudaGetSymbolAddress((void**)&kw,  g_kw);
    cudaGetSymbolAddress((void**)&vw,  g_vw);
    cudaGetSymbolAddress((void**)&hb,  g_h);

    // 1) qkv = x @ Wqkv + bqkv
    sgemm128<<<dim3(C3 / 128, N_TOK / 128), 256>>>(x, Wqkv, bqkv, qkv,
                                                   N_TOK, C3, C_DIM);
    // 2) norm + rope + window scatter
    k_normrope<<<(N_TOK * H_HEADS) / 8, 256>>>(qkv, gq, gk, qw, kw, vw);

    // 3) windowed attention
    const int smem = (64 * 64 + 64 * KST + 64 * 64) * 4;   // 50176 B
    cudaFuncSetAttribute(k_attn, cudaFuncAttributeMaxDynamicSharedMemorySize, smem);
    k_attn<<<NW * H_HEADS * 8, 256, smem>>>(qw, kw, vw, hb);

    // 4) out = h @ Wout + bout
    sgemm128<<<dim3(C_DIM / 128, N_TOK / 128), 256>>>(hb, Wout, bout, out,
                                                      N_TOK, C_DIM, C_DIM);
}

// round 5
// speedup vs baseline: 1.6596x; 1.6596x over previous
#include <cuda_runtime.h>
#include <math.h>

#define N_TOK   32768
#define C_DIM   1024
#define C3      3072
#define H_HEADS 16
#define D_HEAD  64
#define NW      64          // (32/8)^3 windows
#define WSZ     512         // 8^3 tokens per window
#define KST     68          // padded smem stride (floats) for K/P tile

// ---------------- scratch (device globals: no allocation allowed) ----------
__device__ float g_qkv[(size_t)N_TOK * C3];
__device__ float g_qw [(size_t)NW * H_HEADS * WSZ * D_HEAD];
__device__ float g_kw [(size_t)NW * H_HEADS * WSZ * D_HEAD];
__device__ float g_vw [(size_t)NW * H_HEADS * WSZ * D_HEAD];
__device__ float g_h  [(size_t)N_TOK * C_DIM];

// ================= TF32 tensor-core GEMM (low-risk variant) ===============
// C = A @ B + bias.  A:[M,K] row-major, B:[K,N] row-major.
// Block 128x128, BK=16, 8 warps in 4(m) x 2(n), warp tile 32x64.
// mma.sync.m16n8k8.tf32. STATIC smem (~19KB), register-prefetch staging
// (no cp.async, no dynamic smem, no launch attributes).
#define BM   128
#define BN   128
#define BK   16
#define AST  20    // A smem row stride (uints): frag loads conflict-free
#define BST  136   // B smem row stride (uints): frag loads conflict-free

__device__ __forceinline__ unsigned f2tf(float f) {
    unsigned u;
    asm("cvt.rna.tf32.f32 %0, %1;" : "=r"(u) : "f"(f));
    return u;
}
__device__ __forceinline__ void st_tf4(unsigned* p, float4 v) {
    uint4 u = make_uint4(f2tf(v.x), f2tf(v.y), f2tf(v.z), f2tf(v.w));
    *(uint4*)p = u;
}
__device__ __forceinline__ void mma8(float* d, const unsigned* a, const unsigned* b) {
    asm volatile(
        "mma.sync.aligned.m16n8k8.row.col.f32.tf32.tf32.f32 "
        "{%0,%1,%2,%3}, {%4,%5,%6,%7}, {%8,%9}, {%0,%1,%2,%3};"
        : "+f"(d[0]), "+f"(d[1]), "+f"(d[2]), "+f"(d[3])
        : "r"(a[0]), "r"(a[1]), "r"(a[2]), "r"(a[3]), "r"(b[0]), "r"(b[1]));
}

__global__ __launch_bounds__(256) void gemm_tf32(
        const float* __restrict__ A, const float* __restrict__ B,
        const float* __restrict__ bias, float* __restrict__ Cmat,
        int M, int Nn, int K)
{
    __shared__ unsigned As[BM * AST];   // 2560 u32 = 10240 B
    __shared__ unsigned Bs[BK * BST];   // 2176 u32 =  8704 B

    const int t    = threadIdx.x;
    const int lane = t & 31;
    const int w    = t >> 5;
    const int wm   = (w & 3) * 32;
    const int wn   = (w >> 2) * 64;
    const int m0   = blockIdx.y * BM;
    const int n0   = blockIdx.x * BN;
    const int r    = lane >> 2;
    const int c    = lane & 3;

    // staging coordinates
    const int arow = t >> 2;            // 0..63  (rows arow, arow+64)
    const int acol = (t & 3) * 4;       // 0,4,8,12
    const int brow = t >> 4;            // 0..15
    const int bcol = (t & 15) * 4;      // 0..60  (cols bcol, bcol+64)

    const float* Ap0 = A + (size_t)(m0 + arow) * K + acol;
    const float* Ap1 = Ap0 + (size_t)64 * K;
    const float* Bp  = B + (size_t)brow * Nn + n0 + bcol;

    float acc[2][8][4];
    #pragma unroll
    for (int mt = 0; mt < 2; mt++)
        #pragma unroll
        for (int nt = 0; nt < 8; nt++)
            #pragma unroll
            for (int q = 0; q < 4; q++) acc[mt][nt][q] = 0.f;

    const int nslice = K / BK;

    float4 a0 = *(const float4*)(Ap0);
    float4 a1 = *(const float4*)(Ap1);
    float4 b0 = *(const float4*)(Bp);
    float4 b1 = *(const float4*)(Bp + 64);

    for (int s = 0; s < nslice; s++) {
        st_tf4(As + arow * AST + acol,        a0);
        st_tf4(As + (arow + 64) * AST + acol, a1);
        st_tf4(Bs + brow * BST + bcol,        b0);
        st_tf4(Bs + brow * BST + bcol + 64,   b1);
        __syncthreads();

        if (s + 1 < nslice) {                 // prefetch next slice
            const int ko = (s + 1) * BK;
            a0 = *(const float4*)(Ap0 + ko);
            a1 = *(const float4*)(Ap1 + ko);
            const float* bp = Bp + (size_t)ko * Nn;
            b0 = *(const float4*)(bp);
            b1 = *(const float4*)(bp + 64);
        }

        const unsigned* ab = As + (wm + r) * AST + c;
        const unsigned* bb = Bs + c * BST + wn + r;

        #pragma unroll
        for (int ks = 0; ks < 2; ks++) {
            unsigned af[2][4], bf[8][2];
            #pragma unroll
            for (int mt = 0; mt < 2; mt++) {
                const unsigned* p = ab + mt * 16 * AST + ks * 8;
                af[mt][0] = p[0];
                af[mt][1] = p[8 * AST];
                af[mt][2] = p[4];
                af[mt][3] = p[8 * AST + 4];
            }
            #pragma unroll
            for (int nt = 0; nt < 8; nt++) {
                const unsigned* p = bb + ks * 8 * BST + nt * 8;
                bf[nt][0] = p[0];
                bf[nt][1] = p[4 * BST];
            }
            #pragma unroll
            for (int mt = 0; mt < 2; mt++)
                #pragma unroll
                for (int nt = 0; nt < 8; nt++)
                    mma8(acc[mt][nt], af[mt], bf[nt]);
        }
        __syncthreads();
    }

    // epilogue: add bias, write float2 pairs
    #pragma unroll
    for (int mt = 0; mt < 2; mt++) {
        const int mrow = m0 + wm + mt * 16 + r;
        #pragma unroll
        for (int nt = 0; nt < 8; nt++) {
            const int ncol = n0 + wn + nt * 8 + 2 * c;
            const float bb0 = bias[ncol], bb1 = bias[ncol + 1];
            float* p0 = Cmat + (size_t)mrow * Nn + ncol;
            float* p1 = Cmat + (size_t)(mrow + 8) * Nn + ncol;
            *(float2*)p0 = make_float2(acc[mt][nt][0] + bb0, acc[mt][nt][1] + bb1);
            *(float2*)p1 = make_float2(acc[mt][nt][2] + bb0, acc[mt][nt][3] + bb1);
        }
    }
}

// ---------------- K2: RMS-norm + RoPE + window scatter ---------------------
__global__ __launch_bounds__(256) void k_normrope(
        const float* __restrict__ qkv,
        const float* __restrict__ gq, const float* __restrict__ gk,
        float* __restrict__ qw, float* __restrict__ kw, float* __restrict__ vw)
{
    const int t    = threadIdx.x;
    const int wid  = t >> 5;
    const int lane = t & 31;
    const int gw   = blockIdx.x * 8 + wid;      // 0 .. N_TOK*H-1
    const int n    = gw >> 4;
    const int h    = gw & 15;

    const float* p = qkv + (size_t)n * C3 + h * D_HEAD;
    float2 q = *(const float2*)(p + 2 * lane);
    float2 k = *(const float2*)(p + C_DIM + 2 * lane);
    float2 v = *(const float2*)(p + 2 * C_DIM + 2 * lane);

    float sq = q.x * q.x + q.y * q.y;
    float sk = k.x * k.x + k.y * k.y;
    #pragma unroll
    for (int m = 16; m; m >>= 1) {
        sq += __shfl_xor_sync(0xffffffffu, sq, m);
        sk += __shfl_xor_sync(0xffffffffu, sk, m);
    }
    const float invq = 1.0f / fmaxf(sqrtf(sq), 1e-12f);   // 8/norm * 1/8
    const float invk = 8.0f / fmaxf(sqrtf(sk), 1e-12f);

    float2 gqv = *(const float2*)(gq + h * D_HEAD + 2 * lane);
    float2 gkv = *(const float2*)(gk + h * D_HEAD + 2 * lane);
    q.x *= invq * gqv.x;  q.y *= invq * gqv.y;
    k.x *= invk * gkv.x;  k.y *= invk * gkv.y;

    const int gx = n >> 10, gy = (n >> 5) & 31, gz = n & 31;
    float cc = 1.0f, s = 0.0f;
    if (lane < 30) {
        const int axis = lane / 10, f = lane % 10;
        const float freq = expf(-(float)f * 0.9210340371976184f);
        const int coord = (axis == 0) ? gx : (axis == 1) ? gy : gz;
        const float ph = (float)coord * freq;
        cc = cosf(ph);  s = sinf(ph);
    }
    const float q0 = q.x * cc - q.y * s, q1 = q.x * s + q.y * cc;
    const float k0 = k.x * cc - k.y * s, k1 = k.x * s + k.y * cc;

    const int wdw = ((gx >> 3) * 4 + (gy >> 3)) * 4 + (gz >> 3);
    const int pos = ((gx & 7) * 8 + (gy & 7)) * 8 + (gz & 7);
    const size_t ob = ((size_t)(wdw * H_HEADS + h) * WSZ + pos) * D_HEAD + 2 * lane;
    *(float2*)(qw + ob) = make_float2(q0, q1);
    *(float2*)(kw + ob) = make_float2(k0, k1);
    *(float2*)(vw + ob) = v;
}

// ---------------- K3: windowed flash attention -----------------------------
__global__ __launch_bounds__(256) void k_attn(
        const float* __restrict__ Q, const float* __restrict__ Kw,
        const float* __restrict__ Vw, float* __restrict__ hout)
{
    extern __shared__ float smx[];
    float* Qs = smx;                       // [64][64]
    float* Ks = smx + 64 * 64;             // [64][KST]   (reused as P)
    float* Vs = smx + 64 * 64 + 64 * KST;  // [64][64]

    const int t  = threadIdx.x;
    const int tx = t & 15, ty = t >> 4;
    const int b  = blockIdx.x;
    const int wh = b >> 3;                // window*16 + head
    const int qt = b & 7;                 // query tile
    const size_t base = (size_t)wh * WSZ * D_HEAD;

    #pragma unroll
    for (int i = 0; i < 4; i++) {         // load Q tile [64,64]
        int lin = t + 256 * i;
        int row = lin >> 4, c4 = (lin & 15) << 2;
        *(float4*)(Qs + row * 64 + c4) =
            *(const float4*)(Q + base + (size_t)(qt * 64 + row) * 64 + c4);
    }

    float m[4], l[4], O[4][4];
    #pragma unroll
    for (int i = 0; i < 4; i++) {
        m[i] = -3.0e38f; l[i] = 0.f;
        #pragma unroll
        for (int j = 0; j < 4; j++) O[i][j] = 0.f;
    }

    for (int kt = 0; kt < 8; kt++) {
        __syncthreads();
        #pragma unroll
        for (int i = 0; i < 4; i++) {     // load K,V tiles [64,64]
            int lin = t + 256 * i;
            int row = lin >> 4, c4 = (lin & 15) << 2;
            size_t g = base + (size_t)(kt * 64 + row) * 64 + c4;
            *(float4*)(Ks + row * KST + c4) = *(const float4*)(Kw + g);
            *(float4*)(Vs + row * 64  + c4) = *(const float4*)(Vw + g);
        }
        __syncthreads();

        float S[4][4];
        #pragma unroll
        for (int i = 0; i < 4; i++)
            #pragma unroll
            for (int j = 0; j < 4; j++) S[i][j] = 0.f;
        #pragma unroll
        for (int d4 = 0; d4 < 16; d4++) {
            float4 qv[4], kv[4];
            #pragma unroll
            for (int i = 0; i < 4; i++)
                qv[i] = *(const float4*)(Qs + (ty + 16 * i) * 64 + d4 * 4);
            #pragma unroll
            for (int j = 0; j < 4; j++)
                kv[j] = *(const float4*)(Ks + (tx + 16 * j) * KST + d4 * 4);
            #pragma unroll
            for (int i = 0; i < 4; i++)
                #pragma unroll
                for (int j = 0; j < 4; j++)
                    S[i][j] += qv[i].x * kv[j].x + qv[i].y * kv[j].y
                             + qv[i].z * kv[j].z + qv[i].w * kv[j].w;
        }

        float alpha[4];
        #pragma unroll
        for (int i = 0; i < 4; i++) {
            float rm = fmaxf(fmaxf(S[i][0], S[i][1]), fmaxf(S[i][2], S[i][3]));
            #pragma unroll
            for (int mm = 8; mm; mm >>= 1)
                rm = fmaxf(rm, __shfl_xor_sync(0xffffffffu, rm, mm));
            float mn = fmaxf(m[i], rm);
            alpha[i] = __expf(m[i] - mn);
            m[i] = mn;
            float ps = 0.f;
            #pragma unroll
            for (int j = 0; j < 4; j++) { S[i][j] = __expf(S[i][j] - mn); ps += S[i][j]; }
            #pragma unroll
            for (int mm = 8; mm; mm >>= 1)
                ps += __shfl_xor_sync(0xffffffffu, ps, mm);
            l[i] = l[i] * alpha[i] + ps;
        }

        __syncthreads();
        #pragma unroll
        for (int i = 0; i < 4; i++)
            #pragma unroll
            for (int j = 0; j < 4; j++) {
                Ks[(ty + 16 * i) * KST + tx + 16 * j] = S[i][j];  // P tile
                O[i][j] *= alpha[i];
            }
        __syncthreads();

        #pragma unroll
        for (int cc = 0; cc < 16; cc++) {
            float4 pv[4], vv[4];
            #pragma unroll
            for (int i = 0; i < 4; i++)
                pv[i] = *(const float4*)(Ks + (ty + 16 * i) * KST + cc * 4);
            #pragma unroll
            for (int c = 0; c < 4; c++)
                vv[c] = *(const float4*)(Vs + (cc * 4 + c) * 64 + tx * 4);
            #pragma unroll
            for (int i = 0; i < 4; i++) {
                O[i][0] = fmaf(pv[i].x, vv[0].x, O[i][0]);
                O[i][1] = fmaf(pv[i].x, vv[0].y, O[i][1]);
                O[i][2] = fmaf(pv[i].x, vv[0].z, O[i][2]);
                O[i][3] = fmaf(pv[i].x, vv[0].w, O[i][3]);
                O[i][0] = fmaf(pv[i].y, vv[1].x, O[i][0]);
                O[i][1] = fmaf(pv[i].y, vv[1].y, O[i][1]);
                O[i][2] = fmaf(pv[i].y, vv[1].z, O[i][2]);
                O[i][3] = fmaf(pv[i].y, vv[1].w, O[i][3]);
                O[i][0] = fmaf(pv[i].z, vv[2].x, O[i][0]);
                O[i][1] = fmaf(pv[i].z, vv[2].y, O[i][1]);
                O[i][2] = fmaf(pv[i].z, vv[2].z, O[i][2]);
                O[i][3] = fmaf(pv[i].z, vv[2].w, O[i][3]);
                O[i][0] = fmaf(pv[i].w, vv[3].x, O[i][0]);
                O[i][1] = fmaf(pv[i].w, vv[3].y, O[i][1]);
                O[i][2] = fmaf(pv[i].w, vv[3].z, O[i][2]);
                O[i][3] = fmaf(pv[i].w, vv[3].w, O[i][3]);
            }
        }
    }

    const int wdw = wh >> 4, h = wh & 15;
    const int wx = wdw >> 4, wy = (wdw >> 2) & 3, wz = wdw & 3;
    #pragma unroll
    for (int i = 0; i < 4; i++) {
        int p  = qt * 64 + ty + 16 * i;
        int ix = p >> 6, iy = (p >> 3) & 7, iz = p & 7;
        int gx = wx * 8 + ix, gy = wy * 8 + iy, gz = wz * 8 + iz;
        int n  = (gx << 10) + (gy << 5) + gz;
        float inv = 1.0f / l[i];
        *(float4*)(hout + (size_t)n * C_DIM + h * D_HEAD + tx * 4) =
            make_float4(O[i][0] * inv, O[i][1] * inv, O[i][2] * inv, O[i][3] * inv);
    }
}

// ---------------- launch ---------------------------------------------------
extern "C" void kernel_launch(void* const* d_in, const int* in_sizes, int n_in,
                              void* d_out, int out_size)
{
    const float* x    = (const float*)d_in[0];
    // d_in[1] = coords (int32) — derivable from token index, unused
    const float* Wqkv = (const float*)d_in[2];
    const float* bqkv = (const float*)d_in[3];
    const float* gq   = (const float*)d_in[4];
    const float* gk   = (const float*)d_in[5];
    const float* Wout = (const float*)d_in[6];
    const float* bout = (const float*)d_in[7];
    float* out = (float*)d_out;

    float *qkv, *qw, *kw, *vw, *hb;
    cudaGetSymbolAddress((void**)&qkv, g_qkv);
    cudaGetSymbolAddress((void**)&qw,  g_qw);
    cudaGetSymbolAddress((void**)&kw,  g_kw);
    cudaGetSymbolAddress((void**)&vw,  g_vw);
    cudaGetSymbolAddress((void**)&hb,  g_h);

    // 1) qkv = x @ Wqkv + bqkv   (tensor cores, TF32, static smem)
    gemm_tf32<<<dim3(C3 / BN, N_TOK / BM), 256>>>(
        x, Wqkv, bqkv, qkv, N_TOK, C3, C_DIM);

    // 2) norm + rope + window scatter
    k_normrope<<<(N_TOK * H_HEADS) / 8, 256>>>(qkv, gq, gk, qw, kw, vw);

    // 3) windowed attention
    const int smem = (64 * 64 + 64 * KST + 64 * 64) * 4;   // 50176 B
    cudaFuncSetAttribute(k_attn, cudaFuncAttributeMaxDynamicSharedMemorySize, smem);
    k_attn<<<NW * H_HEADS * 8, 256, smem>>>(qw, kw, vw, hb);

    // 4) out = h @ Wout + bout   (tensor cores, TF32, static smem)
    gemm_tf32<<<dim3(C_DIM / BN, N_TOK / BM), 256>>>(
        hb, Wout, bout, out, N_TOK, C_DIM, C_DIM);
}

// round 6
// speedup vs baseline: 2.2590x; 1.3612x over previous
#include <cuda_runtime.h>
#include <math.h>

#define N_TOK   32768
#define C_DIM   1024
#define C3      3072
#define H_HEADS 16
#define D_HEAD  64
#define NW      64          // (32/8)^3 windows
#define WSZ     512         // 8^3 tokens per window

// ---------------- scratch (device globals: no allocation allowed) ----------
__device__ float g_qkv[(size_t)N_TOK * C3];
__device__ float g_qw [(size_t)NW * H_HEADS * WSZ * D_HEAD];
__device__ float g_kw [(size_t)NW * H_HEADS * WSZ * D_HEAD];
__device__ float g_vw [(size_t)NW * H_HEADS * WSZ * D_HEAD];
__device__ float g_h  [(size_t)N_TOK * C_DIM];

// ================= shared TF32 helpers ====================================
__device__ __forceinline__ unsigned f2tf(float f) {
    unsigned u;
    asm("cvt.rna.tf32.f32 %0, %1;" : "=r"(u) : "f"(f));
    return u;
}
__device__ __forceinline__ void st_tf4(unsigned* p, float4 v) {
    uint4 u = make_uint4(f2tf(v.x), f2tf(v.y), f2tf(v.z), f2tf(v.w));
    *(uint4*)p = u;
}
__device__ __forceinline__ void mma8(float* d, const unsigned* a, const unsigned* b) {
    asm volatile(
        "mma.sync.aligned.m16n8k8.row.col.f32.tf32.tf32.f32 "
        "{%0,%1,%2,%3}, {%4,%5,%6,%7}, {%8,%9}, {%0,%1,%2,%3};"
        : "+f"(d[0]), "+f"(d[1]), "+f"(d[2]), "+f"(d[3])
        : "r"(a[0]), "r"(a[1]), "r"(a[2]), "r"(a[3]), "r"(b[0]), "r"(b[1]));
}

// ================= TF32 tensor-core GEMM (unchanged, passing) =============
#define BM   128
#define BN   128
#define BK   16
#define AST  20
#define BST  136

__global__ __launch_bounds__(256) void gemm_tf32(
        const float* __restrict__ A, const float* __restrict__ B,
        const float* __restrict__ bias, float* __restrict__ Cmat,
        int M, int Nn, int K)
{
    __shared__ unsigned As[BM * AST];
    __shared__ unsigned Bs[BK * BST];

    const int t    = threadIdx.x;
    const int lane = t & 31;
    const int w    = t >> 5;
    const int wm   = (w & 3) * 32;
    const int wn   = (w >> 2) * 64;
    const int m0   = blockIdx.y * BM;
    const int n0   = blockIdx.x * BN;
    const int r    = lane >> 2;
    const int c    = lane & 3;

    const int arow = t >> 2;
    const int acol = (t & 3) * 4;
    const int brow = t >> 4;
    const int bcol = (t & 15) * 4;

    const float* Ap0 = A + (size_t)(m0 + arow) * K + acol;
    const float* Ap1 = Ap0 + (size_t)64 * K;
    const float* Bp  = B + (size_t)brow * Nn + n0 + bcol;

    float acc[2][8][4];
    #pragma unroll
    for (int mt = 0; mt < 2; mt++)
        #pragma unroll
        for (int nt = 0; nt < 8; nt++)
            #pragma unroll
            for (int q = 0; q < 4; q++) acc[mt][nt][q] = 0.f;

    const int nslice = K / BK;

    float4 a0 = *(const float4*)(Ap0);
    float4 a1 = *(const float4*)(Ap1);
    float4 b0 = *(const float4*)(Bp);
    float4 b1 = *(const float4*)(Bp + 64);

    for (int s = 0; s < nslice; s++) {
        st_tf4(As + arow * AST + acol,        a0);
        st_tf4(As + (arow + 64) * AST + acol, a1);
        st_tf4(Bs + brow * BST + bcol,        b0);
        st_tf4(Bs + brow * BST + bcol + 64,   b1);
        __syncthreads();

        if (s + 1 < nslice) {
            const int ko = (s + 1) * BK;
            a0 = *(const float4*)(Ap0 + ko);
            a1 = *(const float4*)(Ap1 + ko);
            const float* bp = Bp + (size_t)ko * Nn;
            b0 = *(const float4*)(bp);
            b1 = *(const float4*)(bp + 64);
        }

        const unsigned* ab = As + (wm + r) * AST + c;
        const unsigned* bb = Bs + c * BST + wn + r;

        #pragma unroll
        for (int ks = 0; ks < 2; ks++) {
            unsigned af[2][4], bf[8][2];
            #pragma unroll
            for (int mt = 0; mt < 2; mt++) {
                const unsigned* p = ab + mt * 16 * AST + ks * 8;
                af[mt][0] = p[0];
                af[mt][1] = p[8 * AST];
                af[mt][2] = p[4];
                af[mt][3] = p[8 * AST + 4];
            }
            #pragma unroll
            for (int nt = 0; nt < 8; nt++) {
                const unsigned* p = bb + ks * 8 * BST + nt * 8;
                bf[nt][0] = p[0];
                bf[nt][1] = p[4 * BST];
            }
            #pragma unroll
            for (int mt = 0; mt < 2; mt++)
                #pragma unroll
                for (int nt = 0; nt < 8; nt++)
                    mma8(acc[mt][nt], af[mt], bf[nt]);
        }
        __syncthreads();
    }

    #pragma unroll
    for (int mt = 0; mt < 2; mt++) {
        const int mrow = m0 + wm + mt * 16 + r;
        #pragma unroll
        for (int nt = 0; nt < 8; nt++) {
            const int ncol = n0 + wn + nt * 8 + 2 * c;
            const float bb0 = bias[ncol], bb1 = bias[ncol + 1];
            float* p0 = Cmat + (size_t)mrow * Nn + ncol;
            float* p1 = Cmat + (size_t)(mrow + 8) * Nn + ncol;
            *(float2*)p0 = make_float2(acc[mt][nt][0] + bb0, acc[mt][nt][1] + bb1);
            *(float2*)p1 = make_float2(acc[mt][nt][2] + bb0, acc[mt][nt][3] + bb1);
        }
    }
}

// ---------------- K2: RMS-norm + RoPE + window scatter (unchanged) --------
__global__ __launch_bounds__(256) void k_normrope(
        const float* __restrict__ qkv,
        const float* __restrict__ gq, const float* __restrict__ gk,
        float* __restrict__ qw, float* __restrict__ kw, float* __restrict__ vw)
{
    const int t    = threadIdx.x;
    const int wid  = t >> 5;
    const int lane = t & 31;
    const int gw   = blockIdx.x * 8 + wid;
    const int n    = gw >> 4;
    const int h    = gw & 15;

    const float* p = qkv + (size_t)n * C3 + h * D_HEAD;
    float2 q = *(const float2*)(p + 2 * lane);
    float2 k = *(const float2*)(p + C_DIM + 2 * lane);
    float2 v = *(const float2*)(p + 2 * C_DIM + 2 * lane);

    float sq = q.x * q.x + q.y * q.y;
    float sk = k.x * k.x + k.y * k.y;
    #pragma unroll
    for (int m = 16; m; m >>= 1) {
        sq += __shfl_xor_sync(0xffffffffu, sq, m);
        sk += __shfl_xor_sync(0xffffffffu, sk, m);
    }
    const float invq = 1.0f / fmaxf(sqrtf(sq), 1e-12f);   // 8/norm * 1/8
    const float invk = 8.0f / fmaxf(sqrtf(sk), 1e-12f);

    float2 gqv = *(const float2*)(gq + h * D_HEAD + 2 * lane);
    float2 gkv = *(const float2*)(gk + h * D_HEAD + 2 * lane);
    q.x *= invq * gqv.x;  q.y *= invq * gqv.y;
    k.x *= invk * gkv.x;  k.y *= invk * gkv.y;

    const int gx = n >> 10, gy = (n >> 5) & 31, gz = n & 31;
    float cc = 1.0f, s = 0.0f;
    if (lane < 30) {
        const int axis = lane / 10, f = lane % 10;
        const float freq = expf(-(float)f * 0.9210340371976184f);
        const int coord = (axis == 0) ? gx : (axis == 1) ? gy : gz;
        const float ph = (float)coord * freq;
        cc = cosf(ph);  s = sinf(ph);
    }
    const float q0 = q.x * cc - q.y * s, q1 = q.x * s + q.y * cc;
    const float k0 = k.x * cc - k.y * s, k1 = k.x * s + k.y * cc;

    const int wdw = ((gx >> 3) * 4 + (gy >> 3)) * 4 + (gz >> 3);
    const int pos = ((gx & 7) * 8 + (gy & 7)) * 8 + (gz & 7);
    const size_t ob = ((size_t)(wdw * H_HEADS + h) * WSZ + pos) * D_HEAD + 2 * lane;
    *(float2*)(qw + ob) = make_float2(q0, q1);
    *(float2*)(kw + ob) = make_float2(k0, k1);
    *(float2*)(vw + ob) = v;
}

// ---------------- K3: windowed flash attention on TF32 tensor cores -------
// Block = 256 thr (8 warps), 128 query rows of one (window,head) slab.
// Warp w owns S rows [16w,16w+16). 8 key-tiles of 64, online softmax on
// register fragments, P round-trips smem (stride 68, conflict-free A frags).
#define ATST 68
#define ATTN_SMEM ((128*ATST + 64*ATST + 64*ATST + 128*ATST) * 4)  // 104448 B

__global__ __launch_bounds__(256) void k_attn(
        const float* __restrict__ Q, const float* __restrict__ Kw,
        const float* __restrict__ Vw, float* __restrict__ hout)
{
    extern __shared__ unsigned su[];
    unsigned* Qs = su;                     // [128][68] tf32
    unsigned* Ks = su + 128 * ATST;        // [64][68]
    unsigned* Vs = Ks + 64 * ATST;         // [64][68]
    unsigned* Ps = Vs + 64 * ATST;         // [128][68]

    const int t    = threadIdx.x;
    const int lane = t & 31;
    const int w    = t >> 5;
    const int r    = lane >> 2;
    const int c    = lane & 3;
    const int b    = blockIdx.x;
    const int wh   = b >> 2;               // window*16 + head
    const int qt   = b & 3;                // query tile (128 rows)
    const size_t base = (size_t)wh * WSZ * D_HEAD;

    // load Q tile [128,64] -> tf32 smem
    #pragma unroll
    for (int i = 0; i < 8; i++) {
        int lin = t + 256 * i;
        int row = lin >> 4, c4 = (lin & 15) << 2;
        st_tf4(Qs + row * ATST + c4,
               *(const float4*)(Q + base + (size_t)(qt * 128 + row) * 64 + c4));
    }

    float m[2], l[2], O[8][4];
    m[0] = m[1] = -3.0e38f;  l[0] = l[1] = 0.f;
    #pragma unroll
    for (int j = 0; j < 8; j++)
        #pragma unroll
        for (int q = 0; q < 4; q++) O[j][q] = 0.f;

    for (int kt = 0; kt < 8; kt++) {
        __syncthreads();                   // prev PV done reading Vs/Ps
        #pragma unroll
        for (int i = 0; i < 4; i++) {      // load K,V tiles [64,64]
            int lin = t + 256 * i;
            int row = lin >> 4, c4 = (lin & 15) << 2;
            size_t g = base + (size_t)(kt * 64 + row) * 64 + c4;
            st_tf4(Ks + row * ATST + c4, *(const float4*)(Kw + g));
            st_tf4(Vs + row * ATST + c4, *(const float4*)(Vw + g));
        }
        __syncthreads();

        // ---- S = Q K^T (scale folded into Q) : 8 n-tiles x 8 k-chunks ----
        float s[8][4];
        #pragma unroll
        for (int j = 0; j < 8; j++)
            #pragma unroll
            for (int q = 0; q < 4; q++) s[j][q] = 0.f;

        const unsigned* qb = Qs + (16 * w + r) * ATST + c;
        #pragma unroll
        for (int kk = 0; kk < 8; kk++) {
            unsigned a[4];
            const unsigned* p = qb + kk * 8;
            a[0] = p[0];
            a[1] = p[8 * ATST];
            a[2] = p[4];
            a[3] = p[8 * ATST + 4];
            #pragma unroll
            for (int j = 0; j < 8; j++) {
                unsigned bfr[2];
                const unsigned* kb = Ks + (8 * j + r) * ATST + kk * 8 + c;
                bfr[0] = kb[0];
                bfr[1] = kb[4];
                mma8(s[j], a, bfr);
            }
        }

        // ---- online softmax on fragments (rows r and r+8 of warp tile) ---
        #pragma unroll
        for (int hh = 0; hh < 2; hh++) {
            float rm = -3.0e38f;
            #pragma unroll
            for (int j = 0; j < 8; j++)
                rm = fmaxf(rm, fmaxf(s[j][2 * hh], s[j][2 * hh + 1]));
            rm = fmaxf(rm, __shfl_xor_sync(0xffffffffu, rm, 1));
            rm = fmaxf(rm, __shfl_xor_sync(0xffffffffu, rm, 2));
            float mn = fmaxf(m[hh], rm);
            float al = __expf(m[hh] - mn);
            m[hh] = mn;
            float ps = 0.f;
            #pragma unroll
            for (int j = 0; j < 8; j++) {
                s[j][2 * hh]     = __expf(s[j][2 * hh] - mn);
                s[j][2 * hh + 1] = __expf(s[j][2 * hh + 1] - mn);
                ps += s[j][2 * hh] + s[j][2 * hh + 1];
            }
            ps += __shfl_xor_sync(0xffffffffu, ps, 1);
            ps += __shfl_xor_sync(0xffffffffu, ps, 2);
            l[hh] = l[hh] * al + ps;
            #pragma unroll
            for (int j = 0; j < 8; j++) {
                O[j][2 * hh]     *= al;
                O[j][2 * hh + 1] *= al;
            }
        }

        // ---- store P (tf32) to smem for A-operand reload -----------------
        unsigned* pp = Ps + (16 * w + r) * ATST;
        #pragma unroll
        for (int j = 0; j < 8; j++) {
            *(uint2*)(pp + 8 * j + 2 * c) =
                make_uint2(f2tf(s[j][0]), f2tf(s[j][1]));
            *(uint2*)(pp + 8 * ATST + 8 * j + 2 * c) =
                make_uint2(f2tf(s[j][2]), f2tf(s[j][3]));
        }
        __syncthreads();

        // ---- O += P V ----------------------------------------------------
        const unsigned* pb = Ps + (16 * w + r) * ATST + c;
        #pragma unroll
        for (int kk = 0; kk < 8; kk++) {
            unsigned a[4];
            const unsigned* p = pb + kk * 8;
            a[0] = p[0];
            a[1] = p[8 * ATST];
            a[2] = p[4];
            a[3] = p[8 * ATST + 4];
            #pragma unroll
            for (int j = 0; j < 8; j++) {
                unsigned bfr[2];
                bfr[0] = Vs[(kk * 8 + c) * ATST + 8 * j + r];
                bfr[1] = Vs[(kk * 8 + c + 4) * ATST + 8 * j + r];
                mma8(O[j], a, bfr);
            }
        }
    }

    // ---- epilogue: un-window, divide by l, write --------------------------
    const int wdw = wh >> 4, h = wh & 15;
    const int wx = wdw >> 4, wy = (wdw >> 2) & 3, wz = wdw & 3;
    const float inv0 = 1.0f / l[0];
    const float inv1 = 1.0f / l[1];

    const int p0 = qt * 128 + 16 * w + r;
    const int p1 = p0 + 8;
    int ix = p0 >> 6, iy = (p0 >> 3) & 7, iz = p0 & 7;
    const int n0 = ((wx * 8 + ix) << 10) + ((wy * 8 + iy) << 5) + (wz * 8 + iz);
    ix = p1 >> 6; iy = (p1 >> 3) & 7; iz = p1 & 7;
    const int n1 = ((wx * 8 + ix) << 10) + ((wy * 8 + iy) << 5) + (wz * 8 + iz);

    #pragma unroll
    for (int j = 0; j < 8; j++) {
        const int col = h * D_HEAD + 8 * j + 2 * c;
        *(float2*)(hout + (size_t)n0 * C_DIM + col) =
            make_float2(O[j][0] * inv0, O[j][1] * inv0);
        *(float2*)(hout + (size_t)n1 * C_DIM + col) =
            make_float2(O[j][2] * inv1, O[j][3] * inv1);
    }
}

// ---------------- launch ---------------------------------------------------
extern "C" void kernel_launch(void* const* d_in, const int* in_sizes, int n_in,
                              void* d_out, int out_size)
{
    const float* x    = (const float*)d_in[0];
    // d_in[1] = coords (int32) — derivable from token index, unused
    const float* Wqkv = (const float*)d_in[2];
    const float* bqkv = (const float*)d_in[3];
    const float* gq   = (const float*)d_in[4];
    const float* gk   = (const float*)d_in[5];
    const float* Wout = (const float*)d_in[6];
    const float* bout = (const float*)d_in[7];
    float* out = (float*)d_out;

    float *qkv, *qw, *kw, *vw, *hb;
    cudaGetSymbolAddress((void**)&qkv, g_qkv);
    cudaGetSymbolAddress((void**)&qw,  g_qw);
    cudaGetSymbolAddress((void**)&kw,  g_kw);
    cudaGetSymbolAddress((void**)&vw,  g_vw);
    cudaGetSymbolAddress((void**)&hb,  g_h);

    // 1) qkv = x @ Wqkv + bqkv   (tensor cores, TF32, static smem)
    gemm_tf32<<<dim3(C3 / BN, N_TOK / BM), 256>>>(
        x, Wqkv, bqkv, qkv, N_TOK, C3, C_DIM);

    // 2) norm + rope + window scatter
    k_normrope<<<(N_TOK * H_HEADS) / 8, 256>>>(qkv, gq, gk, qw, kw, vw);

    // 3) windowed attention (tensor cores, TF32)
    cudaFuncSetAttribute(k_attn, cudaFuncAttributeMaxDynamicSharedMemorySize,
                         ATTN_SMEM);
    k_attn<<<NW * H_HEADS * 4, 256, ATTN_SMEM>>>(qw, kw, vw, hb);

    // 4) out = h @ Wout + bout   (tensor cores, TF32, static smem)
    gemm_tf32<<<dim3(C_DIM / BN, N_TOK / BM), 256>>>(
        hb, Wout, bout, out, N_TOK, C_DIM, C_DIM);
}